// round 2
// baseline (speedup 1.0000x reference)
#include <cuda_runtime.h>
#include <math.h>

// Problem constants
static constexpr int kT   = 2048;   // tokens
static constexpr int kH   = 2048;   // hidden
static constexpr int kE   = 64;     // experts
static constexpr int kK   = 8;      // top-k
static constexpr int kI   = 768;    // intermediate
static constexpr int kCAP = 512;    // expert capacity

// ---------------- scratch (device globals; zero-initialized at module load) ----------------
__device__ float g_logits[kT * kE];                      // [T, E]
__device__ int   g_cnt[kE];                              // per-expert slot count
__device__ int   g_slot_tok[kE * kCAP];                  // slot -> token
__device__ float g_slot_w[kE * kCAP];                    // slot -> combine weight
__device__ float g_act[(size_t)kE * kCAP * kI];          // silu(gate)*up, [E, CAP, I]
// rows >= cnt[e] of g_act are never written -> remain 0 from static init (deterministic)

// ---------------- kernel 0: zero output + counters ----------------
__global__ void k_zero(float* __restrict__ out) {
    int n = kT * kH;
    for (int i = blockIdx.x * blockDim.x + threadIdx.x; i < n; i += gridDim.x * blockDim.x)
        out[i] = 0.0f;
    if (blockIdx.x == 0 && threadIdx.x < kE) g_cnt[threadIdx.x] = 0;
}

// ---------------- kernel 1: router logits = x @ w_router^T  ([T,E]) ----------------
__global__ __launch_bounds__(256) void k_router(const float* __restrict__ x,
                                                const float* __restrict__ wr) {
    __shared__ float As[32][64];   // [k][m]  (tokens)
    __shared__ float Bs[32][64];   // [k][n]  (experts)
    const int t0  = blockIdx.x * 64;
    const int tid = threadIdx.x;
    const int tx  = tid & 15;      // -> 4 experts
    const int ty  = tid >> 4;      // -> 4 tokens

    float acc[16];
#pragma unroll
    for (int i = 0; i < 16; i++) acc[i] = 0.0f;

    for (int kt = 0; kt < kH; kt += 32) {
#pragma unroll
        for (int l = 0; l < 2; l++) {
            int idx = tid + l * 256;           // 0..511
            int row = idx >> 3, q = idx & 7;   // 64 rows x 8 float4
            float4 a = *(const float4*)&x[(size_t)(t0 + row) * kH + kt + q * 4];
            As[q * 4 + 0][row] = a.x; As[q * 4 + 1][row] = a.y;
            As[q * 4 + 2][row] = a.z; As[q * 4 + 3][row] = a.w;
            float4 b = *(const float4*)&wr[(size_t)row * kH + kt + q * 4];
            Bs[q * 4 + 0][row] = b.x; Bs[q * 4 + 1][row] = b.y;
            Bs[q * 4 + 2][row] = b.z; Bs[q * 4 + 3][row] = b.w;
        }
        __syncthreads();
#pragma unroll
        for (int k = 0; k < 32; k++) {
            float4 a = *(float4*)&As[k][ty * 4];
            float4 b = *(float4*)&Bs[k][tx * 4];
            float av[4] = {a.x, a.y, a.z, a.w};
            float bv[4] = {b.x, b.y, b.z, b.w};
#pragma unroll
            for (int r = 0; r < 4; r++)
#pragma unroll
                for (int c = 0; c < 4; c++)
                    acc[r * 4 + c] += av[r] * bv[c];
        }
        __syncthreads();
    }
#pragma unroll
    for (int r = 0; r < 4; r++)
#pragma unroll
        for (int c = 0; c < 4; c++)
            g_logits[(size_t)(t0 + ty * 4 + r) * kE + tx * 4 + c] = acc[r * 4 + c];
}

// ---------------- kernel 2: top-8 + renormalize + dispatch ----------------
// softmax -> top-k -> renorm == exp(l - m) / sum_top8 exp(l - m): denominator cancels.
__global__ void k_topk() {
    const int t    = blockIdx.x;
    const int lane = threadIdx.x;  // 32 threads
    float v0 = g_logits[(size_t)t * kE + lane];
    float v1 = g_logits[(size_t)t * kE + lane + 32];

    float m = fmaxf(v0, v1);
#pragma unroll
    for (int o = 16; o; o >>= 1) m = fmaxf(m, __shfl_xor_sync(0xFFFFFFFFu, m, o));

    float a0 = v0, a1 = v1;
    float sel_v[8]; int sel_i[8];
#pragma unroll
    for (int r = 0; r < 8; r++) {
        float bv; int bi;
        if (a0 >= a1) { bv = a0; bi = lane; } else { bv = a1; bi = lane + 32; }
#pragma unroll
        for (int o = 16; o; o >>= 1) {
            float ov = __shfl_xor_sync(0xFFFFFFFFu, bv, o);
            int   oi = __shfl_xor_sync(0xFFFFFFFFu, bi, o);
            if (ov > bv || (ov == bv && oi < bi)) { bv = ov; bi = oi; }
        }
        sel_v[r] = bv; sel_i[r] = bi;
        if (bi == lane)            a0 = -INFINITY;
        else if (bi == lane + 32)  a1 = -INFINITY;
    }
    float ex[8], s = 0.0f;
#pragma unroll
    for (int r = 0; r < 8; r++) { ex[r] = expf(sel_v[r] - m); s += ex[r]; }

    if (lane < 8) {
        float w = ex[lane] / s;
        int   e = sel_i[lane];
        int pos = atomicAdd(&g_cnt[e], 1);
        if (pos < kCAP) {
            g_slot_tok[e * kCAP + pos] = t;
            g_slot_w[e * kCAP + pos]   = w;
        }
    }
}

// ---------------- kernel 3: fused gate+up GEMM with gather + SiLU epilogue ----------------
// per expert e: A = gathered x rows [<=CAP, H];  G = A@Wg, U = A@Wu; act = silu(G)*U
__global__ __launch_bounds__(256) void k_gateup(const float* __restrict__ x,
                                                const float* __restrict__ wg,
                                                const float* __restrict__ wu) {
    const int e = blockIdx.z;
    int cnt = g_cnt[e]; if (cnt > kCAP) cnt = kCAP;
    const int row0 = blockIdx.y * 64;
    if (row0 >= cnt) return;
    const int i0 = blockIdx.x * 64;

    __shared__ float As[32][64];   // [k][m]
    __shared__ float Bg[32][64];   // [k][n]
    __shared__ float Bu[32][64];
    __shared__ int   sTok[64];

    const int tid = threadIdx.x;
    if (tid < 64) {
        int c = row0 + tid;
        sTok[tid] = (c < cnt) ? g_slot_tok[e * kCAP + c] : -1;
    }
    __syncthreads();

    const int tx = tid & 15, ty = tid >> 4;
    float cg[16], cu[16];
#pragma unroll
    for (int i = 0; i < 16; i++) { cg[i] = 0.0f; cu[i] = 0.0f; }

    const float* wgb = wg + (size_t)e * kH * kI + i0;
    const float* wub = wu + (size_t)e * kH * kI + i0;

    for (int kt = 0; kt < kH; kt += 32) {
#pragma unroll
        for (int l = 0; l < 2; l++) {
            int idx = tid + l * 256;                // 0..511
            {   // A gather: 64 rows x 8 float4
                int row = idx >> 3, q = idx & 7;
                int tok = sTok[row];
                float4 v = make_float4(0.f, 0.f, 0.f, 0.f);
                if (tok >= 0) v = *(const float4*)&x[(size_t)tok * kH + kt + q * 4];
                As[q * 4 + 0][row] = v.x; As[q * 4 + 1][row] = v.y;
                As[q * 4 + 2][row] = v.z; As[q * 4 + 3][row] = v.w;
            }
            {   // B tiles: 32 rows x 16 float4 each
                int k = idx >> 4, q = idx & 15;
                float4 vg = *(const float4*)&wgb[(size_t)(kt + k) * kI + q * 4];
                *(float4*)&Bg[k][q * 4] = vg;
                float4 vu = *(const float4*)&wub[(size_t)(kt + k) * kI + q * 4];
                *(float4*)&Bu[k][q * 4] = vu;
            }
        }
        __syncthreads();
#pragma unroll
        for (int k = 0; k < 32; k++) {
            float4 a  = *(float4*)&As[k][ty * 4];
            float4 bg = *(float4*)&Bg[k][tx * 4];
            float4 bu = *(float4*)&Bu[k][tx * 4];
            float av[4] = {a.x, a.y, a.z, a.w};
            float gv[4] = {bg.x, bg.y, bg.z, bg.w};
            float uv[4] = {bu.x, bu.y, bu.z, bu.w};
#pragma unroll
            for (int r = 0; r < 4; r++)
#pragma unroll
                for (int c = 0; c < 4; c++) {
                    cg[r * 4 + c] += av[r] * gv[c];
                    cu[r * 4 + c] += av[r] * uv[c];
                }
        }
        __syncthreads();
    }
#pragma unroll
    for (int r = 0; r < 4; r++) {
        int c = row0 + ty * 4 + r;
        if (c < cnt) {
            float4 o;
            float g0 = cg[r * 4 + 0], g1 = cg[r * 4 + 1], g2 = cg[r * 4 + 2], g3 = cg[r * 4 + 3];
            o.x = (g0 / (1.0f + __expf(-g0))) * cu[r * 4 + 0];
            o.y = (g1 / (1.0f + __expf(-g1))) * cu[r * 4 + 1];
            o.z = (g2 / (1.0f + __expf(-g2))) * cu[r * 4 + 2];
            o.w = (g3 / (1.0f + __expf(-g3))) * cu[r * 4 + 3];
            *(float4*)&g_act[((size_t)e * kCAP + c) * kI + i0 + tx * 4] = o;
        }
    }
}

// ---------------- kernel 4: down GEMM + weighted combine (atomicAdd) ----------------
__global__ __launch_bounds__(256) void k_down(const float* __restrict__ wd,
                                              float* __restrict__ out) {
    const int e = blockIdx.z;
    int cnt = g_cnt[e]; if (cnt > kCAP) cnt = kCAP;
    const int row0 = blockIdx.y * 64;
    if (row0 >= cnt) return;
    const int h0 = blockIdx.x * 64;

    __shared__ float As[32][64];
    __shared__ float Bs[32][64];
    __shared__ int   sTok[64];
    __shared__ float sW[64];

    const int tid = threadIdx.x;
    if (tid < 64) {
        int c = row0 + tid;
        if (c < cnt) { sTok[tid] = g_slot_tok[e * kCAP + c]; sW[tid] = g_slot_w[e * kCAP + c]; }
        else         { sTok[tid] = -1; sW[tid] = 0.0f; }
    }
    __syncthreads();

    const int tx = tid & 15, ty = tid >> 4;
    float acc[16];
#pragma unroll
    for (int i = 0; i < 16; i++) acc[i] = 0.0f;

    const float* wdb = wd + (size_t)e * kI * kH + h0;
    const float* ab  = g_act + (size_t)e * kCAP * kI;

    for (int kt = 0; kt < kI; kt += 32) {
#pragma unroll
        for (int l = 0; l < 2; l++) {
            int idx = tid + l * 256;
            {   int row = idx >> 3, q = idx & 7;
                float4 v = *(const float4*)&ab[(size_t)(row0 + row) * kI + kt + q * 4];
                As[q * 4 + 0][row] = v.x; As[q * 4 + 1][row] = v.y;
                As[q * 4 + 2][row] = v.z; As[q * 4 + 3][row] = v.w;
            }
            {   int k = idx >> 4, q = idx & 15;
                float4 v = *(const float4*)&wdb[(size_t)(kt + k) * kH + q * 4];
                *(float4*)&Bs[k][q * 4] = v;
            }
        }
        __syncthreads();
#pragma unroll
        for (int k = 0; k < 32; k++) {
            float4 a = *(float4*)&As[k][ty * 4];
            float4 b = *(float4*)&Bs[k][tx * 4];
            float av[4] = {a.x, a.y, a.z, a.w};
            float bv[4] = {b.x, b.y, b.z, b.w};
#pragma unroll
            for (int r = 0; r < 4; r++)
#pragma unroll
                for (int c = 0; c < 4; c++)
                    acc[r * 4 + c] += av[r] * bv[c];
        }
        __syncthreads();
    }
#pragma unroll
    for (int r = 0; r < 4; r++) {
        int c = row0 + ty * 4 + r;
        if (c < cnt) {
            int   tok = sTok[ty * 4 + r];
            float w   = sW[ty * 4 + r];
#pragma unroll
            for (int cc = 0; cc < 4; cc++)
                atomicAdd(&out[(size_t)tok * kH + h0 + tx * 4 + cc], w * acc[r * 4 + cc]);
        }
    }
}

// ---------------- launch ----------------
extern "C" void kernel_launch(void* const* d_in, const int* in_sizes, int n_in,
                              void* d_out, int out_size) {
    const float* x  = (const float*)d_in[0];   // hidden_states [T,H]
    const float* wr = (const float*)d_in[1];   // w_router [E,H]
    const float* wg = (const float*)d_in[2];   // w_gate [E,H,I]
    const float* wu = (const float*)d_in[3];   // w_up   [E,H,I]
    const float* wd = (const float*)d_in[4];   // w_down [E,I,H]
    float* out = (float*)d_out;                // [T,H] f32

    k_zero<<<512, 256>>>(out);
    k_router<<<kT / 64, 256>>>(x, wr);
    k_topk<<<kT, 32>>>();
    k_gateup<<<dim3(kI / 64, kCAP / 64, kE), 256>>>(x, wg, wu);
    k_down<<<dim3(kH / 64, kCAP / 64, kE), 256>>>(wd, out);
}

// round 12
// speedup vs baseline: 1.3125x; 1.3125x over previous
#include <cuda_runtime.h>
#include <cuda_bf16.h>
#include <math.h>
#include <stdint.h>

// Problem constants
static constexpr int kT   = 2048;
static constexpr int kH   = 2048;
static constexpr int kE   = 64;
static constexpr int kI   = 768;
static constexpr int kCAP = 512;

// ---------------- device scratch (zero-initialized at module load) ----------------
__device__ float g_logits[kT * kE];
__device__ int   g_cnt[kE];
__device__ int   g_slot_tok[kE * kCAP];
__device__ float g_slot_w[kE * kCAP];
__device__ __nv_bfloat16 g_act_hi[(size_t)kE * kCAP * kI];
__device__ __nv_bfloat16 g_act_lo[(size_t)kE * kCAP * kI];
// rows >= cnt[e] never written -> stay zero (deterministic)

// ---------------- helpers ----------------
__device__ __forceinline__ uint32_t smem_u32(const void* p) {
    uint32_t a;
    asm("{ .reg .u64 t; cvta.to.shared.u64 t, %1; cvt.u32.u64 %0, t; }" : "=r"(a) : "l"(p));
    return a;
}
#define SWZ(x) ((x) ^ (((x) >> 3) & 0x70))

__device__ __forceinline__ void split_bf16(float f, __nv_bfloat16& h, __nv_bfloat16& l) {
    h = __float2bfloat16(f);
    l = __float2bfloat16(f - __bfloat162float(h));
}
__device__ __forceinline__ uint32_t pack2(__nv_bfloat16 a, __nv_bfloat16 b) {
    return (uint32_t)__bfloat16_as_ushort(a) | ((uint32_t)__bfloat16_as_ushort(b) << 16);
}

__device__ __forceinline__ void ldsm4(uint32_t (&r)[4], uint32_t addr) {
    asm volatile("ldmatrix.sync.aligned.m8n8.x4.shared.b16 {%0,%1,%2,%3}, [%4];"
                 : "=r"(r[0]), "=r"(r[1]), "=r"(r[2]), "=r"(r[3]) : "r"(addr));
}
__device__ __forceinline__ void mma16816(float (&d)[4], const uint32_t (&a)[4], uint32_t b0, uint32_t b1) {
    asm volatile("mma.sync.aligned.m16n8k16.row.col.f32.bf16.bf16.f32 "
                 "{%0,%1,%2,%3}, {%4,%5,%6,%7}, {%8,%9}, {%0,%1,%2,%3};"
                 : "+f"(d[0]), "+f"(d[1]), "+f"(d[2]), "+f"(d[3])
                 : "r"(a[0]), "r"(a[1]), "r"(a[2]), "r"(a[3]), "r"(b0), "r"(b1));
}

// smem stage: A_HI(16K) A_LO(16K) B_HI(16K) B_LO(16K)  (A: 128 rows x 64 bf16; B: 128 n-rows x 64 bf16)
static constexpr int STG_A_LO = 16384;
static constexpr int STG_B_HI = 32768;
static constexpr int STG_B_LO = 49152;
static constexpr int SMEM_HDR = 1024;          // sTok[128], sW[128]
static constexpr int SMEM_BYTES = SMEM_HDR + 65536;

// 3-term bf16 MMA over one K=64 chunk; warp tile 32x32; n-tile cols from nb0 (tiles 0,1) and nb1 (tiles 2,3)
// Swizzle is applied per k-step AFTER adding the column offset (col+ks*32 < 128, so the XOR
// stays within the 128B row and matches the store-side SWZ exactly).
__device__ __forceinline__ void compute_chunk(uint32_t aHi, uint32_t aLo, uint32_t bHi, uint32_t bLo,
                                              int wm, int wn, int lane, int nb0, int nb1,
                                              float (&acc)[2][4][4]) {
    const int rA = wm * 32 + (lane & 15);
    const uint32_t mA   = (uint32_t)((rA & 7) << 4);
    const uint32_t baseA0 = (uint32_t)(rA * 128 + ((lane >> 4) & 1) * 16);
    const uint32_t baseA1 = baseA0 + 16 * 128;          // rows +16 (same row&7 -> same mask)
    const int g  = lane >> 3;
    const int rb = ((g >> 1) & 1) * 8 + (lane & 7);
    const uint32_t cB = (uint32_t)((g & 1) * 16);
    const int rB0 = nb0 + rb, rB1 = nb1 + rb;
    const uint32_t mB0 = (uint32_t)((rB0 & 7) << 4);
    const uint32_t mB1 = (uint32_t)((rB1 & 7) << 4);
    const uint32_t baseB0 = (uint32_t)(rB0 * 128) + cB;
    const uint32_t baseB1 = (uint32_t)(rB1 * 128) + cB;
#pragma unroll
    for (int ks = 0; ks < 4; ks++) {
        const uint32_t o = (uint32_t)(ks * 32);
        uint32_t ah[2][4], al[2][4], bh[2][4], bl[2][4];
        ldsm4(ah[0], aHi + ((baseA0 + o) ^ mA));
        ldsm4(ah[1], aHi + ((baseA1 + o) ^ mA));
        ldsm4(al[0], aLo + ((baseA0 + o) ^ mA));
        ldsm4(al[1], aLo + ((baseA1 + o) ^ mA));
        ldsm4(bh[0], bHi + ((baseB0 + o) ^ mB0));
        ldsm4(bh[1], bHi + ((baseB1 + o) ^ mB1));
        ldsm4(bl[0], bLo + ((baseB0 + o) ^ mB0));
        ldsm4(bl[1], bLo + ((baseB1 + o) ^ mB1));
#pragma unroll
        for (int m = 0; m < 2; m++)
#pragma unroll
            for (int t = 0; t < 4; t++) {
                int hsel = t >> 1, rsel = (t & 1) * 2;
                mma16816(acc[m][t], ah[m], bh[hsel][rsel], bh[hsel][rsel + 1]);
                mma16816(acc[m][t], ah[m], bl[hsel][rsel], bl[hsel][rsel + 1]);
                mma16816(acc[m][t], al[m], bh[hsel][rsel], bh[hsel][rsel + 1]);
            }
    }
}

// ---------------- kernel 0: zero output + counters ----------------
__global__ void k_zero(float* __restrict__ out) {
    int n = kT * kH;
    for (int i = blockIdx.x * blockDim.x + threadIdx.x; i < n; i += gridDim.x * blockDim.x)
        out[i] = 0.0f;
    if (blockIdx.x == 0 && threadIdx.x < kE) g_cnt[threadIdx.x] = 0;
}

// ---------------- kernel 1: router logits (fp32 exact) ----------------
__global__ __launch_bounds__(256) void k_router(const float* __restrict__ x,
                                                const float* __restrict__ wr) {
    __shared__ float As[32][64];
    __shared__ float Bs[32][64];
    const int t0  = blockIdx.x * 64;
    const int tid = threadIdx.x;
    const int tx  = tid & 15, ty = tid >> 4;
    float acc[16];
#pragma unroll
    for (int i = 0; i < 16; i++) acc[i] = 0.0f;
    for (int kt = 0; kt < kH; kt += 32) {
#pragma unroll
        for (int l = 0; l < 2; l++) {
            int idx = tid + l * 256;
            int row = idx >> 3, q = idx & 7;
            float4 a = *(const float4*)&x[(size_t)(t0 + row) * kH + kt + q * 4];
            As[q * 4 + 0][row] = a.x; As[q * 4 + 1][row] = a.y;
            As[q * 4 + 2][row] = a.z; As[q * 4 + 3][row] = a.w;
            float4 b = *(const float4*)&wr[(size_t)row * kH + kt + q * 4];
            Bs[q * 4 + 0][row] = b.x; Bs[q * 4 + 1][row] = b.y;
            Bs[q * 4 + 2][row] = b.z; Bs[q * 4 + 3][row] = b.w;
        }
        __syncthreads();
#pragma unroll
        for (int k = 0; k < 32; k++) {
            float4 a = *(float4*)&As[k][ty * 4];
            float4 b = *(float4*)&Bs[k][tx * 4];
            float av[4] = {a.x, a.y, a.z, a.w};
            float bv[4] = {b.x, b.y, b.z, b.w};
#pragma unroll
            for (int r = 0; r < 4; r++)
#pragma unroll
                for (int c = 0; c < 4; c++)
                    acc[r * 4 + c] += av[r] * bv[c];
        }
        __syncthreads();
    }
#pragma unroll
    for (int r = 0; r < 4; r++)
#pragma unroll
        for (int c = 0; c < 4; c++)
            g_logits[(size_t)(t0 + ty * 4 + r) * kE + tx * 4 + c] = acc[r * 4 + c];
}

// ---------------- kernel 2: top-8 + renorm + dispatch ----------------
__global__ void k_topk() {
    const int t    = blockIdx.x;
    const int lane = threadIdx.x;
    float v0 = g_logits[(size_t)t * kE + lane];
    float v1 = g_logits[(size_t)t * kE + lane + 32];
    float m = fmaxf(v0, v1);
#pragma unroll
    for (int o = 16; o; o >>= 1) m = fmaxf(m, __shfl_xor_sync(0xFFFFFFFFu, m, o));
    float a0 = v0, a1 = v1;
    float sel_v[8]; int sel_i[8];
#pragma unroll
    for (int r = 0; r < 8; r++) {
        float bv; int bi;
        if (a0 >= a1) { bv = a0; bi = lane; } else { bv = a1; bi = lane + 32; }
#pragma unroll
        for (int o = 16; o; o >>= 1) {
            float ov = __shfl_xor_sync(0xFFFFFFFFu, bv, o);
            int   oi = __shfl_xor_sync(0xFFFFFFFFu, bi, o);
            if (ov > bv || (ov == bv && oi < bi)) { bv = ov; bi = oi; }
        }
        sel_v[r] = bv; sel_i[r] = bi;
        if (bi == lane)           a0 = -INFINITY;
        else if (bi == lane + 32) a1 = -INFINITY;
    }
    float ex[8], s = 0.0f;
#pragma unroll
    for (int r = 0; r < 8; r++) { ex[r] = expf(sel_v[r] - m); s += ex[r]; }
    if (lane < 8) {
        float w = ex[lane] / s;
        int   e = sel_i[lane];
        int pos = atomicAdd(&g_cnt[e], 1);
        if (pos < kCAP) {
            g_slot_tok[e * kCAP + pos] = t;
            g_slot_w[e * kCAP + pos]   = w;
        }
    }
}

// ---------------- kernel 3: gate+up HMMA GEMM (gather + SiLU epilogue) ----------------
// grid (kI/64, kCAP/128, kE), 512 threads. Block tile M=128, N=128 (64 gate + 64 up), K chunks of 64.
__global__ __launch_bounds__(512, 1) void k_gateup_hmma(const float* __restrict__ x,
                                                        const float* __restrict__ wg,
                                                        const float* __restrict__ wu) {
    const int e = blockIdx.z;
    int cnt = g_cnt[e]; if (cnt > kCAP) cnt = kCAP;
    const int row0 = blockIdx.y * 128;
    if (row0 >= cnt) return;
    const int i0 = blockIdx.x * 64;

    extern __shared__ char sm[];
    int* sTok = (int*)sm;
    char* stg = sm + SMEM_HDR;
    const uint32_t sb = smem_u32(stg);
    const int tid = threadIdx.x;

    if (tid < 128) {
        int c = row0 + tid;
        sTok[tid] = (c < cnt) ? g_slot_tok[e * kCAP + c] : -1;
    }
    __syncthreads();

    const float* wgb = wg + (size_t)e * kH * kI + i0;
    const float* wub = wu + (size_t)e * kH * kI + i0;
    const int lane = tid & 31, wid = tid >> 5, wm = wid >> 2, wn = wid & 3;

    float acc[2][4][4];
#pragma unroll
    for (int m = 0; m < 2; m++)
#pragma unroll
        for (int t = 0; t < 4; t++)
#pragma unroll
            for (int j = 0; j < 4; j++) acc[m][t][j] = 0.0f;

    float4 pA[4], pG[2], pU[2];
    // ---- load chunk 0 ----
#pragma unroll
    for (int i = 0; i < 4; i++) {
        int lin = i * 512 + tid, row = lin >> 4, q = lin & 15;
        int tok = sTok[row];
        pA[i] = (tok >= 0) ? *(const float4*)&x[(size_t)tok * kH + q * 4]
                           : make_float4(0.f, 0.f, 0.f, 0.f);
    }
#pragma unroll
    for (int i = 0; i < 2; i++) {
        int lin = i * 512 + tid, k = lin >> 4, q = lin & 15;
        pG[i] = *(const float4*)&wgb[(size_t)k * kI + q * 4];
        pU[i] = *(const float4*)&wub[(size_t)k * kI + q * 4];
    }
    // store chunk 0
    {
#pragma unroll
        for (int i = 0; i < 4; i++) {
            int lin = i * 512 + tid, row = lin >> 4, q = lin & 15;
            __nv_bfloat16 h0,h1,h2,h3,l0,l1,l2,l3;
            split_bf16(pA[i].x,h0,l0); split_bf16(pA[i].y,h1,l1);
            split_bf16(pA[i].z,h2,l2); split_bf16(pA[i].w,h3,l3);
            uint32_t off = SWZ((uint32_t)(row * 128 + q * 8));
            *(uint2*)(stg + off)            = make_uint2(pack2(h0,h1), pack2(h2,h3));
            *(uint2*)(stg + STG_A_LO + off) = make_uint2(pack2(l0,l1), pack2(l2,l3));
        }
#pragma unroll
        for (int i = 0; i < 2; i++) {
            int lin = i * 512 + tid, k = lin >> 4, q = lin & 15;
            float fg[4] = {pG[i].x, pG[i].y, pG[i].z, pG[i].w};
            float fu[4] = {pU[i].x, pU[i].y, pU[i].z, pU[i].w};
#pragma unroll
            for (int j = 0; j < 4; j++) {
                __nv_bfloat16 h, l;
                split_bf16(fg[j], h, l);
                uint32_t off = SWZ((uint32_t)((q * 4 + j) * 128 + k * 2));
                *(__nv_bfloat16*)(stg + STG_B_HI + off) = h;
                *(__nv_bfloat16*)(stg + STG_B_LO + off) = l;
                split_bf16(fu[j], h, l);
                uint32_t off2 = SWZ((uint32_t)((64 + q * 4 + j) * 128 + k * 2));
                *(__nv_bfloat16*)(stg + STG_B_HI + off2) = h;
                *(__nv_bfloat16*)(stg + STG_B_LO + off2) = l;
            }
        }
    }
    __syncthreads();

    for (int c = 0; c < 32; c++) {
        const bool pf = (c + 1) < 32;
        const int k0n = (c + 1) * 64;
        if (pf) {
#pragma unroll
            for (int i = 0; i < 4; i++) {
                int lin = i * 512 + tid, row = lin >> 4, q = lin & 15;
                int tok = sTok[row];
                pA[i] = (tok >= 0) ? *(const float4*)&x[(size_t)tok * kH + k0n + q * 4]
                                   : make_float4(0.f, 0.f, 0.f, 0.f);
            }
#pragma unroll
            for (int i = 0; i < 2; i++) {
                int lin = i * 512 + tid, k = lin >> 4, q = lin & 15;
                pG[i] = *(const float4*)&wgb[(size_t)(k0n + k) * kI + q * 4];
                pU[i] = *(const float4*)&wub[(size_t)(k0n + k) * kI + q * 4];
            }
        }
        compute_chunk(sb, sb + STG_A_LO, sb + STG_B_HI, sb + STG_B_LO,
                      wm, wn, lane, wn * 16, 64 + wn * 16, acc);
        __syncthreads();
        if (pf) {
#pragma unroll
            for (int i = 0; i < 4; i++) {
                int lin = i * 512 + tid, row = lin >> 4, q = lin & 15;
                __nv_bfloat16 h0,h1,h2,h3,l0,l1,l2,l3;
                split_bf16(pA[i].x,h0,l0); split_bf16(pA[i].y,h1,l1);
                split_bf16(pA[i].z,h2,l2); split_bf16(pA[i].w,h3,l3);
                uint32_t off = SWZ((uint32_t)(row * 128 + q * 8));
                *(uint2*)(stg + off)            = make_uint2(pack2(h0,h1), pack2(h2,h3));
                *(uint2*)(stg + STG_A_LO + off) = make_uint2(pack2(l0,l1), pack2(l2,l3));
            }
#pragma unroll
            for (int i = 0; i < 2; i++) {
                int lin = i * 512 + tid, k = lin >> 4, q = lin & 15;
                float fg[4] = {pG[i].x, pG[i].y, pG[i].z, pG[i].w};
                float fu[4] = {pU[i].x, pU[i].y, pU[i].z, pU[i].w};
#pragma unroll
                for (int j = 0; j < 4; j++) {
                    __nv_bfloat16 h, l;
                    split_bf16(fg[j], h, l);
                    uint32_t off = SWZ((uint32_t)((q * 4 + j) * 128 + k * 2));
                    *(__nv_bfloat16*)(stg + STG_B_HI + off) = h;
                    *(__nv_bfloat16*)(stg + STG_B_LO + off) = l;
                    split_bf16(fu[j], h, l);
                    uint32_t off2 = SWZ((uint32_t)((64 + q * 4 + j) * 128 + k * 2));
                    *(__nv_bfloat16*)(stg + STG_B_HI + off2) = h;
                    *(__nv_bfloat16*)(stg + STG_B_LO + off2) = l;
                }
            }
            __syncthreads();
        }
    }

    // ---- epilogue: act = silu(gate)*up -> bf16 hi/lo ----
    const int qrow = lane >> 2, qcol = (lane & 3) * 2;
#pragma unroll
    for (int m = 0; m < 2; m++) {
        int rbase = row0 + wm * 32 + m * 16;
#pragma unroll
        for (int t = 0; t < 2; t++) {
            int col = i0 + wn * 16 + t * 8 + qcol;
            float g0 = acc[m][t][0], g1 = acc[m][t][1], g2 = acc[m][t][2], g3 = acc[m][t][3];
            float u0 = acc[m][t+2][0], u1 = acc[m][t+2][1], u2 = acc[m][t+2][2], u3 = acc[m][t+2][3];
            int r0 = rbase + qrow, r1 = rbase + qrow + 8;
            if (r0 < cnt) {
                float a0 = g0 * u0 / (1.0f + __expf(-g0));
                float a1 = g1 * u1 / (1.0f + __expf(-g1));
                __nv_bfloat16 h0,l0,h1,l1;
                split_bf16(a0,h0,l0); split_bf16(a1,h1,l1);
                size_t idx = ((size_t)e * kCAP + r0) * kI + col;
                *(uint32_t*)&g_act_hi[idx] = pack2(h0, h1);
                *(uint32_t*)&g_act_lo[idx] = pack2(l0, l1);
            }
            if (r1 < cnt) {
                float a2 = g2 * u2 / (1.0f + __expf(-g2));
                float a3 = g3 * u3 / (1.0f + __expf(-g3));
                __nv_bfloat16 h2,l2,h3,l3;
                split_bf16(a2,h2,l2); split_bf16(a3,h3,l3);
                size_t idx = ((size_t)e * kCAP + r1) * kI + col;
                *(uint32_t*)&g_act_hi[idx] = pack2(h2, h3);
                *(uint32_t*)&g_act_lo[idx] = pack2(l2, l3);
            }
        }
    }
}

// ---------------- kernel 4: down HMMA GEMM + weighted atomic combine ----------------
// grid (kH/128, kCAP/128, kE), 512 threads. Block tile M=128, N=128, K=768 in 12 chunks.
__global__ __launch_bounds__(512, 1) void k_down_hmma(const float* __restrict__ wd,
                                                      float* __restrict__ out) {
    const int e = blockIdx.z;
    int cnt = g_cnt[e]; if (cnt > kCAP) cnt = kCAP;
    const int row0 = blockIdx.y * 128;
    if (row0 >= cnt) return;
    const int h0 = blockIdx.x * 128;

    extern __shared__ char sm[];
    int*   sTok = (int*)sm;
    float* sW   = (float*)(sm + 512);
    char*  stg  = sm + SMEM_HDR;
    const uint32_t sb = smem_u32(stg);
    const int tid = threadIdx.x;

    if (tid < 128) {
        int c = row0 + tid;
        if (c < cnt) { sTok[tid] = g_slot_tok[e * kCAP + c]; sW[tid] = g_slot_w[e * kCAP + c]; }
        else         { sTok[tid] = -1;                        sW[tid] = 0.0f; }
    }
    __syncthreads();

    const float* wdb = wd + (size_t)e * kI * kH + h0;
    const __nv_bfloat16* ahb = g_act_hi + ((size_t)e * kCAP + row0) * kI;
    const __nv_bfloat16* alb = g_act_lo + ((size_t)e * kCAP + row0) * kI;
    const int lane = tid & 31, wid = tid >> 5, wm = wid >> 2, wn = wid & 3;

    float acc[2][4][4];
#pragma unroll
    for (int m = 0; m < 2; m++)
#pragma unroll
        for (int t = 0; t < 4; t++)
#pragma unroll
            for (int j = 0; j < 4; j++) acc[m][t][j] = 0.0f;

    uint4 pH[2], pL[2]; float4 pB[4];
    // ---- chunk 0 ----
#pragma unroll
    for (int i = 0; i < 2; i++) {
        int lin = i * 512 + tid, row = lin >> 3, q = lin & 7;
        pH[i] = *(const uint4*)&ahb[(size_t)row * kI + q * 8];
        pL[i] = *(const uint4*)&alb[(size_t)row * kI + q * 8];
    }
#pragma unroll
    for (int i = 0; i < 4; i++) {
        int lin = i * 512 + tid, k = lin >> 5, q = lin & 31;
        pB[i] = *(const float4*)&wdb[(size_t)k * kH + q * 4];
    }
    {
#pragma unroll
        for (int i = 0; i < 2; i++) {
            int lin = i * 512 + tid, row = lin >> 3, q = lin & 7;
            uint32_t off = SWZ((uint32_t)(row * 128 + q * 16));
            *(uint4*)(stg + off)            = pH[i];
            *(uint4*)(stg + STG_A_LO + off) = pL[i];
        }
#pragma unroll
        for (int i = 0; i < 4; i++) {
            int lin = i * 512 + tid, k = lin >> 5, q = lin & 31;
            float f[4] = {pB[i].x, pB[i].y, pB[i].z, pB[i].w};
#pragma unroll
            for (int j = 0; j < 4; j++) {
                __nv_bfloat16 h, l; split_bf16(f[j], h, l);
                uint32_t off = SWZ((uint32_t)((q * 4 + j) * 128 + k * 2));
                *(__nv_bfloat16*)(stg + STG_B_HI + off) = h;
                *(__nv_bfloat16*)(stg + STG_B_LO + off) = l;
            }
        }
    }
    __syncthreads();

    for (int c = 0; c < 12; c++) {
        const bool pf = (c + 1) < 12;
        const int k0n = (c + 1) * 64;
        if (pf) {
#pragma unroll
            for (int i = 0; i < 2; i++) {
                int lin = i * 512 + tid, row = lin >> 3, q = lin & 7;
                pH[i] = *(const uint4*)&ahb[(size_t)row * kI + k0n + q * 8];
                pL[i] = *(const uint4*)&alb[(size_t)row * kI + k0n + q * 8];
            }
#pragma unroll
            for (int i = 0; i < 4; i++) {
                int lin = i * 512 + tid, k = lin >> 5, q = lin & 31;
                pB[i] = *(const float4*)&wdb[(size_t)(k0n + k) * kH + q * 4];
            }
        }
        compute_chunk(sb, sb + STG_A_LO, sb + STG_B_HI, sb + STG_B_LO,
                      wm, wn, lane, wn * 32, wn * 32 + 16, acc);
        __syncthreads();
        if (pf) {
#pragma unroll
            for (int i = 0; i < 2; i++) {
                int lin = i * 512 + tid, row = lin >> 3, q = lin & 7;
                uint32_t off = SWZ((uint32_t)(row * 128 + q * 16));
                *(uint4*)(stg + off)            = pH[i];
                *(uint4*)(stg + STG_A_LO + off) = pL[i];
            }
#pragma unroll
            for (int i = 0; i < 4; i++) {
                int lin = i * 512 + tid, k = lin >> 5, q = lin & 31;
                float f[4] = {pB[i].x, pB[i].y, pB[i].z, pB[i].w};
#pragma unroll
                for (int j = 0; j < 4; j++) {
                    __nv_bfloat16 h, l; split_bf16(f[j], h, l);
                    uint32_t off = SWZ((uint32_t)((q * 4 + j) * 128 + k * 2));
                    *(__nv_bfloat16*)(stg + STG_B_HI + off) = h;
                    *(__nv_bfloat16*)(stg + STG_B_LO + off) = l;
                }
            }
            __syncthreads();
        }
    }

    // ---- epilogue: out[tok] += w * y ----
    const int qrow = lane >> 2, qcol = (lane & 3) * 2;
#pragma unroll
    for (int m = 0; m < 2; m++) {
        int rrel = wm * 32 + m * 16 + qrow;
#pragma unroll
        for (int t = 0; t < 4; t++) {
            int col = h0 + wn * 32 + t * 8 + qcol;
            int s0 = row0 + rrel, s1 = s0 + 8;
            if (s0 < cnt) {
                int tok = sTok[rrel]; float w = sW[rrel];
                float* o = out + (size_t)tok * kH + col;
                atomicAdd(&o[0], w * acc[m][t][0]);
                atomicAdd(&o[1], w * acc[m][t][1]);
            }
            if (s1 < cnt) {
                int tok = sTok[rrel + 8]; float w = sW[rrel + 8];
                float* o = out + (size_t)tok * kH + col;
                atomicAdd(&o[0], w * acc[m][t][2]);
                atomicAdd(&o[1], w * acc[m][t][3]);
            }
        }
    }
}

// ---------------- launch ----------------
extern "C" void kernel_launch(void* const* d_in, const int* in_sizes, int n_in,
                              void* d_out, int out_size) {
    const float* x  = (const float*)d_in[0];
    const float* wr = (const float*)d_in[1];
    const float* wg = (const float*)d_in[2];
    const float* wu = (const float*)d_in[3];
    const float* wd = (const float*)d_in[4];
    float* out = (float*)d_out;

    cudaFuncSetAttribute(k_gateup_hmma, cudaFuncAttributeMaxDynamicSharedMemorySize, SMEM_BYTES);
    cudaFuncSetAttribute(k_down_hmma,   cudaFuncAttributeMaxDynamicSharedMemorySize, SMEM_BYTES);

    k_zero<<<512, 256>>>(out);
    k_router<<<kT / 64, 256>>>(x, wr);
    k_topk<<<kT, 32>>>();
    k_gateup_hmma<<<dim3(kI / 64, kCAP / 128, kE), 512, SMEM_BYTES>>>(x, wg, wu);
    k_down_hmma<<<dim3(kH / 128, kCAP / 128, kE), 512, SMEM_BYTES>>>(wd, out);
}